// round 7
// baseline (speedup 1.0000x reference)
#include <cuda_runtime.h>

#define BB      512
#define INF     512
#define OUTF    64
#define KK      16
#define NN      1024   // OUTF * KK
#define OUTCOLS 576    // INF + OUTF
#define THRESH  120.0f

typedef unsigned long long ull;

// Scratch (static device allocs are allowed).
__device__ float g_M[BB * NN];              // 2MB: M = x @ T
__device__ float g_G[OUTF * BB * 8];        // 1MB: 8 group-sums per (o,i)

#define FMA2D(d, a, b, c) \
    asm("fma.rn.f32x2 %0, %1, %2, %3;" : "=l"(d) : "l"(a), "l"(b), "l"(c))
#define ADD2(d, a, b) \
    asm("add.rn.f32x2 %0, %1, %2;" : "=l"(d) : "l"(a), "l"(b))

__device__ __forceinline__ void mma_tf32(float* c, const unsigned* a, const unsigned* b) {
    asm("mma.sync.aligned.m16n8k8.row.col.f32.tf32.tf32.f32 "
        "{%0,%1,%2,%3}, {%4,%5,%6,%7}, {%8,%9}, {%0,%1,%2,%3};"
        : "+f"(c[0]), "+f"(c[1]), "+f"(c[2]), "+f"(c[3])
        : "r"(a[0]), "r"(a[1]), "r"(a[2]), "r"(a[3]), "r"(b[0]), "r"(b[1]));
}

// ---------------------------------------------------------------------------
// GEMM via tf32 tensor cores, double-buffered: M = x(512x512) @ T(512x1024).
// Block 256 thr (8 warps), tile 16x64 (warp = n8 slice), k-tile 32.
// Grid (16,32) = 512 blocks -> ~28 warps/SM.
// Epilogue writes g_M + group sums g_G; zero-inits out[:,512:576].
// ---------------------------------------------------------------------------
__global__ __launch_bounds__(256) void gemm_tc(const float* __restrict__ x,
                                               const float* __restrict__ T,
                                               float* __restrict__ out) {
    __shared__ float As[2][16][36];
    __shared__ float Bs[2][32][68];

    const int tid  = threadIdx.x;
    const int warp = tid >> 5;     // 0..7, owns cols [warp*8, warp*8+8)
    const int lane = tid & 31;
    const int tg   = lane >> 2;    // 0..7
    const int tig  = lane & 3;     // 0..3

    const int rowBase = blockIdx.y * 16;
    const int colBase = blockIdx.x * 64;

    // Zero-init the o_b region of out (32768 elements over 512 blocks).
    {
        int idx = (blockIdx.y * 16 + blockIdx.x) * 64 + (tid & 63);
        if (tid < 64) out[(idx >> 6) * OUTCOLS + INF + (idx & 63)] = 0.f;
    }

    const int ar  = tid >> 3;            // A row (0..15) for tid<128
    const int akq = (tid & 7) * 4;       // A k-quad
    const int bk  = tid >> 4;            // B k row (0..15, +16)
    const int bnq = (tid & 15) * 4;      // B n-quad

    // Prologue: tile 0 -> buffer 0.
    if (tid < 128)
        *(float4*)&As[0][ar][akq] = *(const float4*)&x[(rowBase + ar) * INF + akq];
    *(float4*)&Bs[0][bk][bnq]      = *(const float4*)&T[bk * NN + colBase + bnq];
    *(float4*)&Bs[0][bk + 16][bnq] = *(const float4*)&T[(bk + 16) * NN + colBase + bnq];
    __syncthreads();

    float acc[4] = {0.f, 0.f, 0.f, 0.f};
    float4 pa, pb0, pb1;

    for (int it = 0; it < 16; ++it) {
        const int cur = it & 1;
        const int nxt = cur ^ 1;
        const int k0n = (it + 1) * 32;

        if (it < 15) {
            if (tid < 128)
                pa = *(const float4*)&x[(rowBase + ar) * INF + k0n + akq];
            pb0 = *(const float4*)&T[(k0n + bk) * NN + colBase + bnq];
            pb1 = *(const float4*)&T[(k0n + bk + 16) * NN + colBase + bnq];
        }

#pragma unroll
        for (int ks = 0; ks < 32; ks += 8) {
            unsigned a[4], b[2];
            a[0] = __float_as_uint(As[cur][tg][ks + tig]);
            a[1] = __float_as_uint(As[cur][tg + 8][ks + tig]);
            a[2] = __float_as_uint(As[cur][tg][ks + tig + 4]);
            a[3] = __float_as_uint(As[cur][tg + 8][ks + tig + 4]);
            int colB = warp * 8 + tg;
            b[0] = __float_as_uint(Bs[cur][ks + tig][colB]);
            b[1] = __float_as_uint(Bs[cur][ks + tig + 4][colB]);
            mma_tf32(acc, a, b);
        }

        if (it < 15) {
            if (tid < 128)
                *(float4*)&As[nxt][ar][akq] = pa;
            *(float4*)&Bs[nxt][bk][bnq]      = pb0;
            *(float4*)&Bs[nxt][bk + 16][bnq] = pb1;
            __syncthreads();
        }
    }

    // Epilogue: g_M + adjacent-pair group sums g_G.
    {
        int row0 = rowBase + tg;
        int col0 = colBase + warp * 8 + tig * 2;
        int o = col0 >> 4;
        int g = (col0 & 15) >> 1;
        *(float2*)&g_M[row0 * NN + col0]       = make_float2(acc[0], acc[1]);
        *(float2*)&g_M[(row0 + 8) * NN + col0] = make_float2(acc[2], acc[3]);
        g_G[((o << 9) + row0) * 8 + g]     = acc[0] + acc[1];
        g_G[((o << 9) + row0 + 8) * 8 + g] = acc[2] + acc[3];
    }
}

// ---------------------------------------------------------------------------
// Fused filter + exact: grid (65, 8), 512 threads.
//   o < 64 : block (o, ec): i = tid, j in [ec*64, ec*64+64), j > i only.
//            lb filter on group sums; survivors -> exact exp(-L1) from the
//            smem M j-tile; atomicAdd into out[i,o] and out[j,o].
//   o == 64: copy x rows into out[:, 0:512].
// ---------------------------------------------------------------------------
__global__ __launch_bounds__(512) void stage12(const float* __restrict__ x,
                                               float* __restrict__ out) {
    __shared__ __align__(16) ull   sG[64 * 4];    // 2 KB group sums (packed pairs)
    __shared__ __align__(16) float sM[64 * KK];   // 4 KB M j-tile

    const int o   = blockIdx.x;
    const int ec  = blockIdx.y;
    const int tid = threadIdx.x;

    if (o == OUTF) {
        int base = ec * 64;
#pragma unroll
        for (int t = tid; t < 64 * (INF / 4); t += 512) {
            int r = t >> 7;
            int c = t & 127;
            float4 v = *(const float4*)&x[(base + r) * INF + c * 4];
            *(float4*)&out[(base + r) * OUTCOLS + c * 4] = v;
        }
        return;
    }

    const int jbase = ec * 64;
    const int i     = tid;
    const int lim   = i - jbase;   // bits jj <= lim are cleared (keep j > i)

    if (tid < 128) {
        int r = tid >> 1;
        int h = tid & 1;
        *(float4*)&sG[r * 4 + h * 2] =
            *(const float4*)&g_G[((o << 9) + jbase + r) * 8 + h * 4];
    } else if (tid < 384) {
        int t = tid - 128;           // 0..255
        int r = t >> 2;
        int q = t & 3;
        *(float4*)&sM[r * KK + q * 4] =
            *(const float4*)&g_M[(jbase + r) * NN + o * KK + q * 4];
    }

    ull gi[4];
    {
        const ulonglong2* p = (const ulonglong2*)&g_G[((o << 9) + i) * 8];
        ulonglong2 v0 = p[0], v1 = p[1];
        gi[0] = v0.x; gi[1] = v0.y; gi[2] = v1.x; gi[3] = v1.y;
    }
    __syncthreads();

    const ull NEG1  = 0xBF800000BF800000ULL;
    const ull AMASK = 0x7FFFFFFF7FFFFFFFULL;

    ull msk = 0;
    if (lim < 63) {
#pragma unroll
        for (int jj = 0; jj < 64; ++jj) {
            const ulonglong2* p = (const ulonglong2*)&sG[jj * 4];
            ulonglong2 v0 = p[0], v1 = p[1];

            ull d0, d1, d2, d3;
            FMA2D(d0, v0.x, NEG1, gi[0]);
            FMA2D(d1, v0.y, NEG1, gi[1]);
            FMA2D(d2, v1.x, NEG1, gi[2]);
            FMA2D(d3, v1.y, NEG1, gi[3]);
            d0 &= AMASK; d1 &= AMASK; d2 &= AMASK; d3 &= AMASK;

            ull s0, s1, t;
            ADD2(s0, d0, d1);
            ADD2(s1, d2, d3);
            ADD2(t, s0, s1);

            float lb = __uint_as_float((unsigned)t) + __uint_as_float((unsigned)(t >> 32));
            if (lb < THRESH) msk |= (1ULL << jj);
        }
        if (lim >= 0) msk &= ~((2ULL << lim) - 1ULL);
    }

    if (!msk) return;

    // Exact pass for survivors (rare): own row from global, j-row from smem.
    const float4* ri = (const float4*)&g_M[i * NN + o * KK];
    float4 a = ri[0], b = ri[1], c = ri[2], d = ri[3];

    float acc = 0.f;
    while (msk) {
        int bit = __ffsll((long long)msk) - 1;
        msk &= msk - 1;

        const float4* rj = (const float4*)&sM[bit * KK];
        float4 e = rj[0], f = rj[1], g = rj[2], h = rj[3];

        float norm =
            fabsf(a.x - e.x) + fabsf(a.y - e.y) + fabsf(a.z - e.z) + fabsf(a.w - e.w) +
            fabsf(b.x - f.x) + fabsf(b.y - f.y) + fabsf(b.z - f.z) + fabsf(b.w - f.w) +
            fabsf(c.x - g.x) + fabsf(c.y - g.y) + fabsf(c.z - g.z) + fabsf(c.w - g.w) +
            fabsf(d.x - h.x) + fabsf(d.y - h.y) + fabsf(d.z - h.z) + fabsf(d.w - h.w);

        float ev = __expf(-norm);
        if (ev != 0.f) {
            acc += ev;
            atomicAdd(&out[(jbase + bit) * OUTCOLS + INF + o], ev);
        }
    }
    if (acc != 0.f)
        atomicAdd(&out[i * OUTCOLS + INF + o], acc);
}

extern "C" void kernel_launch(void* const* d_in, const int* in_sizes, int n_in,
                              void* d_out, int out_size) {
    const float* x = (const float*)d_in[0];
    const float* T = (const float*)d_in[1];
    float* out = (float*)d_out;

    gemm_tc<<<dim3(NN / 64, BB / 16), 256>>>(x, T, out);
    stage12<<<dim3(OUTF + 1, 8), 512>>>(x, out);
}